// round 8
// baseline (speedup 1.0000x reference)
#include <cuda_runtime.h>
#include <cuda_bf16.h>
#include <math.h>

// TOF PET forward projection. Grid 128^3, box [-200,200]^3, voxel 3.125mm,
// 128 samples/LOR, TOF sigma=30mm, cutoff 90mm, bin=5.
//
// FOUR LORs per warp (8-lane subgroups). Per-sample quantities are affine in
// sample index k; Gaussian evaluated in u-space: w = exp2(-u*u),
// u = fmaf(fk,du,u0), cutoff |u|<=UTHR. The active k-window is computed
// EXACTLY w.r.t. that fp predicate: fast-div estimate refined by evaluating
// the loop's own fmaf at candidate boundaries (+-1 suffices; the [0,127]
// clamp absorbs estimate error whenever the true boundary is off-range).
// Interior samples therefore need no cutoff test; the single per-sample
// predicate is the lane-overshoot tail guard fk<=khi (required: overshoot
// lanes past k=127 can still be inside the TOF cutoff).

#define GRID_N   128
// TOF_BIN / sqrt(2*pi*TOF_SIGMA2), double-computed, rounded to f32
#define TOF_NORM 0.06649038006690422f
// sC = sqrt(log2(e)/1800); dev^2*log2e/1800 == (dev*sC)^2
#define SC_U     0.028310727f
// 90 * SC_U
#define UTHR     2.5479655f
#define FLT_MIN_NORM 1.1754944e-38f

__global__ __launch_bounds__(256)
void proj_kernel(const float* __restrict__ image,
                 const float* __restrict__ lors,
                 float* __restrict__ out,
                 int n_lors)
{
    const int warp_id = (blockIdx.x * blockDim.x + threadIdx.x) >> 5;
    const int lane    = threadIdx.x & 31;
    const int sub     = lane & 7;            // lane within 8-lane subgroup
    if (warp_id * 4 >= n_lors) return;
    int lor = warp_id * 4 + (lane >> 3);
    const bool live = (lor < n_lors);
    if (!live) lor = 0;                      // dummy work, no store

    // ---- per-LOR setup (uniform across each 8-lane subgroup) ----
    const float* l7 = lors + (size_t)lor * 7;
    const float p1x = l7[0], p1y = l7[1], p1z = l7[2];
    const float dx  = l7[3] - p1x;
    const float dy  = l7[4] - p1y;
    const float dz  = l7[5] - p1z;
    const float tof = l7[6];

    const float L = sqrtf(fmaf(dx, dx, fmaf(dy, dy, dz * dz)));

    // safe_d = where(|d| < 1e-8, 1e-8, d)  (matches reference: +eps)
    const float eps = 1e-8f;
    const float sdx = (fabsf(dx) < eps) ? eps : dx;
    const float sdy = (fabsf(dy) < eps) ? eps : dy;
    const float sdz = (fabsf(dz) < eps) ? eps : dz;

    // slab intersection via fast reciprocals (~2ulp)
    const float rx = __fdividef(1.0f, sdx);
    const float ry = __fdividef(1.0f, sdy);
    const float rz = __fdividef(1.0f, sdz);
    const float tax = (-200.0f - p1x) * rx, tbx = (200.0f - p1x) * rx;
    const float tay = (-200.0f - p1y) * ry, tby = (200.0f - p1y) * ry;
    const float taz = (-200.0f - p1z) * rz, tbz = (200.0f - p1z) * rz;

    float tmin = fmaxf(fmaxf(fminf(tax, tbx), fminf(tay, tby)), fminf(taz, tbz));
    tmin = fmaxf(tmin, 0.0f);
    float tmax = fminf(fminf(fmaxf(tax, tbx), fmaxf(tay, tby)), fmaxf(taz, tbz));
    tmax = fminf(tmax, 1.0f);

    const float valid = (tmax > tmin) ? 1.0f : 0.0f;
    const float span  = fmaxf(tmax - tmin, 0.0f);

    // ---- affine-in-k coefficients ----
    const float cs = span * 0.0078125f;          // dt per sample
    const float t0 = fmaf(0.5f, cs, tmin);       // t at k=0
    const float dL   = cs * L;                   // d(dev)/dk (>= 0)
    const float dev0 = fmaf(t0 - 0.5f, L, -tof); // dev at k=0
    const float du   = dL   * SC_U;              // u slope (>= 0)
    const float u0   = dev0 * SC_U;              // u at k=0
    const float gsx = cs * dx * 0.32f;
    const float gsy = cs * dy * 0.32f;
    const float gsz = cs * dz * 0.32f;
    const float gx0 = (fmaf(t0, dx, p1x) + 200.0f) * 0.32f;
    const float gy0 = (fmaf(t0, dy, p1y) + 200.0f) * 0.32f;
    const float gz0 = (fmaf(t0, dz, p1z) + 200.0f) * 0.32f;

    // ---- exact active k-window for predicate |fmaf(fk,du,u0)| <= UTHR ----
    float kl, kh;
    if (du > FLT_MIN_NORM) {
        const float rdu = __fdividef(1.0f, du);
        // upper boundary: largest k with u(k) <= UTHR (u monotone increasing)
        kh = floorf((UTHR - u0) * rdu);
        kh = (fmaf(kh + 1.0f, du, u0) <= UTHR) ? kh + 1.0f : kh;
        kh = (fmaf(kh,        du, u0) <= UTHR) ? kh        : kh - 1.0f;
        // lower boundary: smallest k with u(k) >= -UTHR
        kl = ceilf((-UTHR - u0) * rdu);
        kl = (fmaf(kl - 1.0f, du, u0) >= -UTHR) ? kl - 1.0f : kl;
        kl = (fmaf(kl,        du, u0) >= -UTHR) ? kl        : kl + 1.0f;
    } else {
        // u(k) == u0 for all k (FTZ): all pass or none
        kl = 0.0f;
        kh = (fabsf(u0) <= UTHR) ? 127.0f : -1.0f;
    }
    const float klo_f = fmaxf(kl, 0.0f);      // +inf collapses via F2I sat
    const float khi_f = fminf(kh, 127.0f);    // -inf -> very negative
    const int klo = (int)klo_f;
    const int khi = (int)khi_f;

    int niter = ((khi - klo) >> 3) + 1;       // <=0 when window empty
    if (!(tmax > tmin)) niter = 0;            // skip box-missing rays
    float fk = klo_f + (float)sub;            // exact small ints
    float acc = 0.0f;

    #pragma unroll 4
    for (; niter > 0; --niter) {
        if (fk <= khi_f) {                    // lane-overshoot tail guard
            // lower clamp via fabs (free modifier; true coords never <= -1,
            // only rounding -eps -> +eps -> floor 0 == clamp); upper via
            // fminf(.,127.99) (128.0 -> 127 == clamp)
            const int ix = __float2int_rd(fminf(fabsf(fmaf(fk, gsx, gx0)), 127.99f));
            const int iy = __float2int_rd(fminf(fabsf(fmaf(fk, gsy, gy0)), 127.99f));
            const int iz = __float2int_rd(fminf(fabsf(fmaf(fk, gsz, gz0)), 127.99f));
            const float u = fmaf(fk, du, u0);
            const float val = __ldg(&image[ix * 16384 + iy * 128 + iz]);
            const float w = exp2f(-u * u);
            acc = fmaf(val, w, acc);
        }
        fk += 8.0f;
    }

    // ---- 8-lane subgroup reduction ----
    #pragma unroll
    for (int off = 4; off > 0; off >>= 1)
        acc += __shfl_xor_sync(0xFFFFFFFFu, acc, off);

    if (sub == 0 && live) {
        const float step = span * L * (1.0f / 128.0f);
        out[lor] = acc * TOF_NORM * step * valid;
    }
}

extern "C" void kernel_launch(void* const* d_in, const int* in_sizes, int n_in,
                              void* d_out, int out_size)
{
    const float* image = (const float*)d_in[0];
    const float* lors  = (const float*)d_in[1];
    float* out = (float*)d_out;
    const int n_lors = in_sizes[1] / 7;

    const int threads = 256;                       // 8 warps = 32 LORs/block
    const int n_warps = (n_lors + 3) / 4;
    const int blocks  = (n_warps * 32 + threads - 1) / threads;
    proj_kernel<<<blocks, threads>>>(image, lors, out, n_lors);
}

// round 9
// speedup vs baseline: 1.0997x; 1.0997x over previous
#include <cuda_runtime.h>
#include <cuda_bf16.h>
#include <math.h>

// TOF PET forward projection. Grid 128^3, box [-200,200]^3, voxel 3.125mm,
// 128 samples/LOR, TOF sigma=30mm, cutoff 90mm, bin=5.
//
// FOUR LORs per warp (8-lane subgroups); uniform per-LOR setup is SIMD
// across 4 LORs. Per-sample quantities are affine in sample index k.
// Gaussian weights via geometric recurrence (u^2 has constant second
// difference in k): w(k+8) = w(k)*r(k), r(k+8) = r(k)*C with
// C = exp2(-128*du^2) -- 2 FMULs/sample instead of FMUL+EX2, removing all
// per-sample MUFU pressure (EX2 rt=8/SMSP was co-binding with alu).
// Active k-window computed analytically (widened +-1); per-sample
// predicates: |u|<=UTHR (exact cutoff) AND fk<=127 (tail guard -- required,
// see R5 failure: overshoot lanes past k=127 can still pass the cutoff).

#define GRID_N   128
// TOF_BIN / sqrt(2*pi*TOF_SIGMA2), double-computed, rounded to f32
#define TOF_NORM 0.06649038006690422f
// sC = sqrt(log2(e)/1800); dev^2*log2e/1800 == (dev*sC)^2
#define SC_U     0.028310727f
// 90 * SC_U
#define UTHR     2.5479655f

__global__ __launch_bounds__(256)
void proj_kernel(const float* __restrict__ image,
                 const float* __restrict__ lors,
                 float* __restrict__ out,
                 int n_lors)
{
    const int warp_id = (blockIdx.x * blockDim.x + threadIdx.x) >> 5;
    const int lane    = threadIdx.x & 31;
    const int sub     = lane & 7;            // lane within 8-lane subgroup
    if (warp_id * 4 >= n_lors) return;
    int lor = warp_id * 4 + (lane >> 3);
    const bool live = (lor < n_lors);
    if (!live) lor = 0;                      // dummy work, no store

    // ---- per-LOR setup (uniform across each 8-lane subgroup) ----
    const float* l7 = lors + (size_t)lor * 7;
    const float p1x = l7[0], p1y = l7[1], p1z = l7[2];
    const float dx  = l7[3] - p1x;
    const float dy  = l7[4] - p1y;
    const float dz  = l7[5] - p1z;
    const float tof = l7[6];

    const float L = sqrtf(fmaf(dx, dx, fmaf(dy, dy, dz * dz)));

    // safe_d = where(|d| < 1e-8, 1e-8, d)  (matches reference: +eps)
    const float eps = 1e-8f;
    const float sdx = (fabsf(dx) < eps) ? eps : dx;
    const float sdy = (fabsf(dy) < eps) ? eps : dy;
    const float sdz = (fabsf(dz) < eps) ? eps : dz;

    // slab intersection via fast reciprocals (~2ulp)
    const float rx = __fdividef(1.0f, sdx);
    const float ry = __fdividef(1.0f, sdy);
    const float rz = __fdividef(1.0f, sdz);
    const float tax = (-200.0f - p1x) * rx, tbx = (200.0f - p1x) * rx;
    const float tay = (-200.0f - p1y) * ry, tby = (200.0f - p1y) * ry;
    const float taz = (-200.0f - p1z) * rz, tbz = (200.0f - p1z) * rz;

    float tmin = fmaxf(fmaxf(fminf(tax, tbx), fminf(tay, tby)), fminf(taz, tbz));
    tmin = fmaxf(tmin, 0.0f);
    float tmax = fminf(fminf(fmaxf(tax, tbx), fmaxf(tay, tby)), fmaxf(taz, tbz));
    tmax = fminf(tmax, 1.0f);

    const float valid = (tmax > tmin) ? 1.0f : 0.0f;
    const float span  = fmaxf(tmax - tmin, 0.0f);

    // ---- affine-in-k coefficients ----
    const float cs = span * 0.0078125f;          // dt per sample
    const float t0 = fmaf(0.5f, cs, tmin);       // t at k=0
    const float dL   = cs * L;                   // d(dev)/dk (>= 0)
    const float dev0 = fmaf(t0 - 0.5f, L, -tof); // dev at k=0
    const float du   = dL   * SC_U;              // u slope (>= 0)
    const float u0   = dev0 * SC_U;              // u at k=0
    const float gsx = cs * dx * 0.32f;
    const float gsy = cs * dy * 0.32f;
    const float gsz = cs * dz * 0.32f;
    const float gx0 = (fmaf(t0, dx, p1x) + 200.0f) * 0.32f;
    const float gy0 = (fmaf(t0, dy, p1y) + 200.0f) * 0.32f;
    const float gz0 = (fmaf(t0, dz, p1z) + 200.0f) * 0.32f;

    // ---- active k-window: |dev0 + fk*dL| <= 90, dL >= 0. Widened +-1.
    // Degenerate dL=0 -> rdL=inf: NaN/inf bounds collapse correctly via
    // fmaxf/fminf and F2I saturation.
    const float rdL = __fdividef(1.0f, dL);
    const float klo_f = floorf((-90.0f - dev0) * rdL) - 1.0f;
    const float khi_f = ceilf (( 90.0f - dev0) * rdL) + 1.0f;
    const int klo = (int)fmaxf(klo_f, 0.0f);    // fmaxf(NaN,0)=0
    const int khi = (int)fminf(khi_f, 127.0f);  // fminf(NaN,127)=127

    int niter = ((khi - klo) >> 3) + 1;          // <=0 when window empty
    if (!(tmax > tmin)) niter = 0;               // skip box-missing rays
    float fk = (float)(klo + sub);               // exact small ints
    float acc = 0.0f;

    // ---- Gaussian recurrence init (2 EX2 per lane, then FMULs only) ----
    const float u_a = fmaf(fk, du, u0);
    const float u_b = fmaf(8.0f, du, u_a);       // u at fk+8
    float w = exp2f(-u_a * u_a);
    float r = exp2f(fmaf(u_a, u_a, -u_b * u_b)); // w(k+8)/w(k)
    const float C = exp2f(-128.0f * du * du);    // r(k+8)/r(k)

    #pragma unroll 2
    for (; niter > 0; --niter) {
        const float u = fmaf(fk, du, u0);
        if (fabsf(u) <= UTHR && fk <= 127.0f) {
            // lower clamp via fabs (true coords never <= -1, only rounding
            // -eps -> +eps -> floor 0 == clamp); upper via fminf(.,127.99)
            const int ix = __float2int_rd(fminf(fabsf(fmaf(fk, gsx, gx0)), 127.99f));
            const int iy = __float2int_rd(fminf(fabsf(fmaf(fk, gsy, gy0)), 127.99f));
            const int iz = __float2int_rd(fminf(fabsf(fmaf(fk, gsz, gz0)), 127.99f));
            const float val = __ldg(&image[ix * 16384 + iy * 128 + iz]);
            acc = fmaf(val, w, acc);
        }
        w *= r;
        r *= C;
        fk += 8.0f;
    }

    // ---- 8-lane subgroup reduction ----
    #pragma unroll
    for (int off = 4; off > 0; off >>= 1)
        acc += __shfl_xor_sync(0xFFFFFFFFu, acc, off);

    if (sub == 0 && live) {
        const float step = span * L * (1.0f / 128.0f);
        out[lor] = acc * TOF_NORM * step * valid;
    }
}

extern "C" void kernel_launch(void* const* d_in, const int* in_sizes, int n_in,
                              void* d_out, int out_size)
{
    const float* image = (const float*)d_in[0];
    const float* lors  = (const float*)d_in[1];
    float* out = (float*)d_out;
    const int n_lors = in_sizes[1] / 7;

    const int threads = 256;                       // 8 warps = 32 LORs/block
    const int n_warps = (n_lors + 3) / 4;
    const int blocks  = (n_warps * 32 + threads - 1) / threads;
    proj_kernel<<<blocks, threads>>>(image, lors, out, n_lors);
}